// round 15
// baseline (speedup 1.0000x reference)
#include <cuda_runtime.h>

#define S 1024
#define G 10
#define F 5
#define B 8
#define C 3
#define KW (2*F+1)
#define RPB 2                 // rows per deform block
#define NXB (S / 256)         // x-positions per thread (4)
#define YCHUNKS 8
#define YROWS (S / YCHUNKS)

// Per-row y-interpolated coarse field: (gx, gy) for each (b, y, j)
__device__ float2 g_rows[B][S][G];

// ---------------------------------------------------------------------------
// Prep: separable 11x11 edge-clamped conv (outer-product Gaussian) of the
// 10x10 offsets, clip, then y-interp into per-row fields. grid=(B, YCHUNKS).
// Signals PDL completion when done.
// ---------------------------------------------------------------------------
__global__ __launch_bounds__(256) void prep_kernel(const float* __restrict__ ox,
                                                   const float* __restrict__ oy,
                                                   const float* __restrict__ w,
                                                   const void* __restrict__ mm_p) {
    __shared__ float sh[2][G][G];   // horizontal pass
    __shared__ float sc[2][G][G];   // full smoothed+clipped field

    const int b     = blockIdx.x;
    const int chunk = blockIdx.y;
    const int tid   = threadIdx.x;

    // Phase 1: horizontal pass h[ch][i][j] = sum_v w[F][v] * o[i][clamp(j+v-F)]
    if (tid < 2 * G * G) {
        int ch  = tid / (G * G);
        int rem = tid % (G * G);
        int i   = rem / G;
        int j   = rem % G;
        const float* o = (ch ? oy : ox) + b * G * G + i * G;
        float acc = 0.0f;
        #pragma unroll
        for (int v = 0; v < KW; v++) {
            int jj = min(max(j + v - F, 0), G - 1);
            acc = fmaf(__ldg(&w[F * KW + v]), __ldg(&o[jj]), acc);
        }
        sh[ch][i][j] = acc;
    }
    __syncthreads();

    // Phase 2: vertical pass, scale + clip (separable: w[u][v]=w[u][F]*w[F][v]/w[F][F])
    if (tid < 2 * G * G) {
        int ch  = tid / (G * G);
        int rem = tid % (G * G);
        int i   = rem / G;
        int j   = rem % G;

        int raw = *(const int*)mm_p;   // int32 or float32 — decode robustly
        float mmv = (raw >= 0 && raw < 1000000) ? (float)raw : __int_as_float(raw);
        float max_offset = 2.0f * mmv / (float)S;

        float wff = __ldg(&w[F * KW + F]);
        float acc = 0.0f;
        #pragma unroll
        for (int u = 0; u < KW; u++) {
            int ii = min(max(i + u - F, 0), G - 1);
            acc = fmaf(__ldg(&w[u * KW + F]), sh[ch][ii][j], acc);
        }
        acc *= max_offset / wff;
        acc = fminf(fmaxf(acc, -max_offset), max_offset);
        sc[ch][i][j] = acc;
    }
    __syncthreads();

    // Phase 3: expand along y for this chunk of rows
    for (int k = tid; k < YROWS * G; k += 256) {
        int yl = k / G;
        int j  = k % G;
        int y  = chunk * YROWS + yl;

        float srcy = fmaxf((y + 0.5f) * ((float)G / (float)S) - 0.5f, 0.0f);
        int i0 = min((int)srcy, G - 1);
        int i1 = min(i0 + 1, G - 1);
        float wr = srcy - (float)i0;

        float gx = sc[0][i0][j] * (1.0f - wr) + sc[0][i1][j] * wr;
        float gy = sc[1][i0][j] * (1.0f - wr) + sc[1][i1][j] * wr;
        g_rows[b][y][j] = make_float2(gx, gy);
    }

    // PDL: make writes visible, then allow the dependent grid to proceed.
    __threadfence();
    cudaTriggerProgrammaticLaunchCompletion();
}

// ---------------------------------------------------------------------------
// Deform: one block per (2 rows, batch); prologue-free. Strided pixel mapping
// (x = tid + 256*p): warp-coalesced gathers + streaming (__stcs) stores so the
// write-once output does not evict the gather working set from L2.
// ---------------------------------------------------------------------------
__global__ __launch_bounds__(256, 4) void deform_kernel(const float* __restrict__ xin,
                                                        float* __restrict__ out) {
    __shared__ float2 srow[RPB][G];

    const int b     = blockIdx.y;
    const int ybase = blockIdx.x * RPB;
    const int tid   = threadIdx.x;

    // Wait for prep's g_rows (PDL dependency).
    cudaGridDependencySynchronize();

    if (tid < RPB * G) {
        int r = tid / G;
        int j = tid % G;
        srow[r][j] = g_rows[b][ybase + r][j];
    }
    __syncthreads();

    const float* xb = xin + b * (C * S * S);
    float* obase    = out + b * (C * S * S);

    float Py[RPB];
    #pragma unroll
    for (int r = 0; r < RPB; r++)
        Py[r] = fmaf((float)(ybase + r), 2.0f / (float)(S - 1), -1.0f);

    #pragma unroll
    for (int p = 0; p < NXB; p++) {
        const int x = tid + p * 256;

        // x-dependent field interp — shared across the RPB rows
        float srcx = fmaxf((x + 0.5f) * ((float)G / (float)S) - 0.5f, 0.0f);
        int j0 = min((int)srcx, G - 1);
        int j1 = min(j0 + 1, G - 1);
        float wc  = srcx - (float)j0;
        float wcm = 1.0f - wc;
        float Px  = fmaf((float)x, 2.0f / (float)(S - 1), -1.0f);

        #pragma unroll
        for (int r = 0; r < RPB; r++) {
            float2 fa = srow[r][j0];
            float2 fb = srow[r][j1];
            float gx = fa.x * wcm + fb.x * wc;
            float gy = fa.y * wcm + fb.y * wc;

            float g0 = fminf(fmaxf(gx + Px, -1.0f), 1.0f);
            float g1 = fminf(fmaxf(gy + Py[r], -1.0f), 1.0f);

            // ((g+1)*S - 1) / 2 == g*512 + 511.5
            float ix = fmaf(g0, 512.0f, 511.5f);
            float iy = fmaf(g1, 512.0f, 511.5f);

            float fx = floorf(ix);
            float fy = floorf(iy);
            int x0 = (int)fx;
            int y0 = (int)fy;
            float wx = ix - fx;
            float wy = iy - fy;
            int x1 = x0 + 1;
            int y1 = y0 + 1;

            // ix in [-0.5, 1023.5]: only low of x0 / high of x1 can be OOB
            float wxa = (x0 >= 0)     ? (1.0f - wx) : 0.0f;
            float wxb = (x1 <= S - 1) ? wx          : 0.0f;
            float wya = (y0 >= 0)     ? (1.0f - wy) : 0.0f;
            float wyb = (y1 <= S - 1) ? wy          : 0.0f;

            int cx0 = max(x0, 0);
            int cx1 = min(x1, S - 1);
            int cy0 = max(y0, 0);
            int cy1 = min(y1, S - 1);

            float w00 = wya * wxa;
            float w01 = wya * wxb;
            float w10 = wyb * wxa;
            float w11 = wyb * wxb;

            // Derive neighbor offsets with adds (dx in {0,1}, dyS in {0,S})
            int dx  = cx1 - cx0;
            int dyS = (cy1 - cy0) * S;
            int o00 = cy0 * S + cx0;
            int o01 = o00 + dx;
            int o10 = o00 + dyS;
            int o11 = o10 + dx;

            int orow = (ybase + r) * S + x;

            #pragma unroll
            for (int c = 0; c < C; c++) {
                const float* img = xb + c * (S * S);
                float v = img[o00] * w00 + img[o01] * w01
                        + img[o10] * w10 + img[o11] * w11;
                // Streaming store: output is write-once; keep L2 for gathers.
                __stcs(&obase[c * (S * S) + orow], v);
            }
        }
    }
}

extern "C" void kernel_launch(void* const* d_in, const int* in_sizes, int n_in,
                              void* d_out, int out_size) {
    const float* x  = (const float*)d_in[0];
    const float* ox = (const float*)d_in[1];
    const float* oy = (const float*)d_in[2];
    const float* w  = (const float*)d_in[3];
    const void*  mm = d_in[4];

    prep_kernel<<<dim3(B, YCHUNKS), 256>>>(ox, oy, w, mm);

    // PDL launch of deform.
    cudaLaunchConfig_t cfg = {};
    cfg.gridDim  = dim3(S / RPB, B);
    cfg.blockDim = dim3(256, 1, 1);
    cfg.dynamicSmemBytes = 0;
    cfg.stream = 0;

    cudaLaunchAttribute attr[1];
    attr[0].id = cudaLaunchAttributeProgrammaticStreamSerialization;
    attr[0].val.programmaticStreamSerializationAllowed = 1;
    cfg.attrs = attr;
    cfg.numAttrs = 1;

    cudaLaunchKernelEx(&cfg, deform_kernel, x, (float*)d_out);
}

// round 17
// speedup vs baseline: 1.0490x; 1.0490x over previous
#include <cuda_runtime.h>

#define S 1024
#define G 10
#define F 5
#define B 8
#define C 3
#define KW (2*F+1)
#define RPB 2                 // rows per deform block
#define NXB (S / 256)         // x-positions per thread (4)

// Smoothed+clipped coarse offset field: [batch][{x,y}][G][G]  (800 B)
__device__ float g_sc[B][2][G][G];

// ---------------------------------------------------------------------------
// Prep: separable 11x11 edge-clamped conv (outer-product Gaussian) of the
// 10x10 offsets + clip. grid=(B), 256 threads. Tiny; signals PDL when done.
// ---------------------------------------------------------------------------
__global__ __launch_bounds__(256) void prep_kernel(const float* __restrict__ ox,
                                                   const float* __restrict__ oy,
                                                   const float* __restrict__ w,
                                                   const void* __restrict__ mm_p) {
    __shared__ float sh[2][G][G];   // horizontal pass

    const int b   = blockIdx.x;
    const int tid = threadIdx.x;

    // Phase 1: horizontal pass h[ch][i][j] = sum_v w[F][v] * o[i][clamp(j+v-F)]
    if (tid < 2 * G * G) {
        int ch  = tid / (G * G);
        int rem = tid % (G * G);
        int i   = rem / G;
        int j   = rem % G;
        const float* o = (ch ? oy : ox) + b * G * G + i * G;
        float acc = 0.0f;
        #pragma unroll
        for (int v = 0; v < KW; v++) {
            int jj = min(max(j + v - F, 0), G - 1);
            acc = fmaf(__ldg(&w[F * KW + v]), __ldg(&o[jj]), acc);
        }
        sh[ch][i][j] = acc;
    }
    __syncthreads();

    // Phase 2: vertical pass, scale + clip (separable: w[u][v]=w[u][F]*w[F][v]/w[F][F])
    if (tid < 2 * G * G) {
        int ch  = tid / (G * G);
        int rem = tid % (G * G);
        int i   = rem / G;
        int j   = rem % G;

        int raw = *(const int*)mm_p;   // int32 or float32 — decode robustly
        float mmv = (raw >= 0 && raw < 1000000) ? (float)raw : __int_as_float(raw);
        float max_offset = 2.0f * mmv / (float)S;

        float wff = __ldg(&w[F * KW + F]);
        float acc = 0.0f;
        #pragma unroll
        for (int u = 0; u < KW; u++) {
            int ii = min(max(i + u - F, 0), G - 1);
            acc = fmaf(__ldg(&w[u * KW + F]), sh[ch][ii][j], acc);
        }
        acc *= max_offset / wff;
        acc = fminf(fmaxf(acc, -max_offset), max_offset);
        g_sc[b][ch][i][j] = acc;
    }

    // PDL: make writes visible, then allow the dependent grid to proceed.
    __threadfence();
    cudaTriggerProgrammaticLaunchCompletion();
}

// ---------------------------------------------------------------------------
// Deform: one block per (2 rows, batch). Prologue: 20 threads y-interp the
// 800B coarse field for this block's rows. Main loop: strided pixel mapping
// (x = tid + 256*p), warp-coalesced gathers/stores, interior fast path.
// ---------------------------------------------------------------------------
__global__ __launch_bounds__(256, 4) void deform_kernel(const float* __restrict__ xin,
                                                        float* __restrict__ out) {
    __shared__ float2 srow[RPB][G];

    const int b     = blockIdx.y;
    const int ybase = blockIdx.x * RPB;
    const int tid   = threadIdx.x;

    // Wait for prep's g_sc (PDL dependency).
    cudaGridDependencySynchronize();

    if (tid < RPB * G) {
        int r = tid / G;
        int j = tid % G;
        int y = ybase + r;
        float srcy = fmaxf((y + 0.5f) * ((float)G / (float)S) - 0.5f, 0.0f);
        int i0 = min((int)srcy, G - 1);
        int i1 = min(i0 + 1, G - 1);
        float wr  = srcy - (float)i0;
        float wrm = 1.0f - wr;
        float gx = g_sc[b][0][i0][j] * wrm + g_sc[b][0][i1][j] * wr;
        float gy = g_sc[b][1][i0][j] * wrm + g_sc[b][1][i1][j] * wr;
        srow[r][j] = make_float2(gx, gy);
    }
    __syncthreads();

    const float* xb = xin + b * (C * S * S);
    float* obase    = out + b * (C * S * S);

    float Py[RPB];
    #pragma unroll
    for (int r = 0; r < RPB; r++)
        Py[r] = fmaf((float)(ybase + r), 2.0f / (float)(S - 1), -1.0f);

    #pragma unroll
    for (int p = 0; p < NXB; p++) {
        const int x = tid + p * 256;

        // x-dependent field interp — shared across the RPB rows
        float srcx = fmaxf((x + 0.5f) * ((float)G / (float)S) - 0.5f, 0.0f);
        int j0 = min((int)srcx, G - 1);
        int j1 = min(j0 + 1, G - 1);
        float wc  = srcx - (float)j0;
        float wcm = 1.0f - wc;
        float Px  = fmaf((float)x, 2.0f / (float)(S - 1), -1.0f);

        #pragma unroll
        for (int r = 0; r < RPB; r++) {
            float2 fa = srow[r][j0];
            float2 fb = srow[r][j1];
            float gx = fa.x * wcm + fb.x * wc;
            float gy = fa.y * wcm + fb.y * wc;

            float g0 = fminf(fmaxf(gx + Px, -1.0f), 1.0f);
            float g1 = fminf(fmaxf(gy + Py[r], -1.0f), 1.0f);

            // ((g+1)*S - 1) / 2 == g*512 + 511.5
            float ix = fmaf(g0, 512.0f, 511.5f);
            float iy = fmaf(g1, 512.0f, 511.5f);

            float fx = floorf(ix);
            float fy = floorf(iy);
            int x0 = (int)fx;
            int y0 = (int)fy;
            float wx = ix - fx;
            float wy = iy - fy;

            float w00, w01, w10, w11;
            int o00, o01, o10, o11;

            if (((x0 | y0) >= 0) & (x0 < S - 1) & (y0 < S - 1)) {
                // Interior fast path (vast majority; warp-coherent)
                float wxm = 1.0f - wx;
                float wym = 1.0f - wy;
                w00 = wym * wxm;
                w01 = wym * wx;
                w10 = wy * wxm;
                w11 = wy * wx;
                o00 = y0 * S + x0;
                o01 = o00 + 1;
                o10 = o00 + S;
                o11 = o10 + 1;
            } else {
                int x1 = x0 + 1;
                int y1 = y0 + 1;
                // ix in [-0.5, 1023.5]: only low of x0 / high of x1 can be OOB
                float wxa = (x0 >= 0)     ? (1.0f - wx) : 0.0f;
                float wxb = (x1 <= S - 1) ? wx          : 0.0f;
                float wya = (y0 >= 0)     ? (1.0f - wy) : 0.0f;
                float wyb = (y1 <= S - 1) ? wy          : 0.0f;

                int cx0 = max(x0, 0);
                int cx1 = min(x1, S - 1);
                int cy0 = max(y0, 0);
                int cy1 = min(y1, S - 1);

                w00 = wya * wxa;
                w01 = wya * wxb;
                w10 = wyb * wxa;
                w11 = wyb * wxb;

                int dx  = cx1 - cx0;
                int dyS = (cy1 - cy0) * S;
                o00 = cy0 * S + cx0;
                o01 = o00 + dx;
                o10 = o00 + dyS;
                o11 = o10 + dx;
            }

            int orow = (ybase + r) * S + x;

            #pragma unroll
            for (int c = 0; c < C; c++) {
                const float* img = xb + c * (S * S);
                float v = img[o00] * w00 + img[o01] * w01
                        + img[o10] * w10 + img[o11] * w11;
                obase[c * (S * S) + orow] = v;
            }
        }
    }
}

extern "C" void kernel_launch(void* const* d_in, const int* in_sizes, int n_in,
                              void* d_out, int out_size) {
    const float* x  = (const float*)d_in[0];
    const float* ox = (const float*)d_in[1];
    const float* oy = (const float*)d_in[2];
    const float* w  = (const float*)d_in[3];
    const void*  mm = d_in[4];

    prep_kernel<<<B, 256>>>(ox, oy, w, mm);

    // PDL launch of deform.
    cudaLaunchConfig_t cfg = {};
    cfg.gridDim  = dim3(S / RPB, B);
    cfg.blockDim = dim3(256, 1, 1);
    cfg.dynamicSmemBytes = 0;
    cfg.stream = 0;

    cudaLaunchAttribute attr[1];
    attr[0].id = cudaLaunchAttributeProgrammaticStreamSerialization;
    attr[0].val.programmaticStreamSerializationAllowed = 1;
    cfg.attrs = attr;
    cfg.numAttrs = 1;

    cudaLaunchKernelEx(&cfg, deform_kernel, x, (float*)d_out);
}